// round 15
// baseline (speedup 1.0000x reference)
#include <cuda_runtime.h>
#include <cuda_bf16.h>
#include <math.h>
#include <stdint.h>

#define EPS_BN 1e-5f

// ---------------- scratch ----------------
#define OFF_RGB   0
#define OFF_DEPTH 6422528      // 256*49*512
#define OFF_MM    12845056
#define OFF_LIDAR 17039360
__device__ float g_H[21233664];
__device__ float g_newxyz[256 * 128 * 3];
__device__ float g_pe[16777216];                 // pe2 relu-term [B*128, 512]

// pre-split activations X (concat rgb|depth|mm|lidar), [41472, 512] bf16 hi/lo
__device__ __nv_bfloat16 g_xh[21233664];
__device__ __nv_bfloat16 g_xl[21233664];

// pre-split weights (hi/lo bf16)
#define W_PE2_OFF (4 * 512 * 512)
#define W_TOTAL   (4 * 512 * 512 + 512 * 128)
__device__ __nv_bfloat16 g_wh[W_TOTAL];
__device__ __nv_bfloat16 g_wl[W_TOTAL];
// folded pos-enc layer1 coeffs
__device__ float g_peA[128 * 4];
// block-diagonal mix weight [128, 192] bf16 hi/lo + row bias
__device__ __nv_bfloat16 g_mwh[128 * 192];
__device__ __nv_bfloat16 g_mwl[128 * 192];
__device__ float g_mlb[128];
// transposed H: [b, o, l192] bf16 hi/lo
__device__ __nv_bfloat16 g_hth[256 * 512 * 192];
__device__ __nv_bfloat16 g_htl[256 * 512 * 192];

// ---------------- helpers ----------------
__device__ __forceinline__ uint32_t smem_u32(const void* p) {
    uint32_t a;
    asm("{ .reg .u64 t; cvta.to.shared.u64 t, %1; cvt.u32.u64 %0, t; }" : "=r"(a) : "l"(p));
    return a;
}
__device__ __forceinline__ void cp16(uint32_t dst, const void* src) {
    asm volatile("cp.async.cg.shared.global [%0], [%1], 16;" :: "r"(dst), "l"(src));
}
#define CP_COMMIT() asm volatile("cp.async.commit_group;" ::: "memory")
#define CP_WAIT0()  asm volatile("cp.async.wait_group 0;" ::: "memory")
#define CP_WAIT1()  asm volatile("cp.async.wait_group 1;" ::: "memory")

__device__ __forceinline__ void mma_bf16(float* c, const uint32_t* a, const uint32_t* b) {
    asm volatile(
        "mma.sync.aligned.m16n8k16.row.col.f32.bf16.bf16.f32 "
        "{%0,%1,%2,%3}, {%4,%5,%6,%7}, {%8,%9}, {%0,%1,%2,%3};"
        : "+f"(c[0]), "+f"(c[1]), "+f"(c[2]), "+f"(c[3])
        : "r"(a[0]), "r"(a[1]), "r"(a[2]), "r"(a[3]), "r"(b[0]), "r"(b[1]));
}
#define LDSM_X4(r0, r1, r2, r3, addr)                                        \
    asm volatile("ldmatrix.sync.aligned.m8n8.x4.shared.b16 {%0,%1,%2,%3}, [%4];" \
                 : "=r"(r0), "=r"(r1), "=r"(r2), "=r"(r3) : "r"(addr))
#define LDSM_X2(r0, r1, addr)                                                \
    asm volatile("ldmatrix.sync.aligned.m8n8.x2.shared.b16 {%0,%1}, [%2];"   \
                 : "=r"(r0), "=r"(r1) : "r"(addr))

#define TILE_BYTES 16384
#define GEMM_SMEM 98304         // old core (pe2)
#define MIX_SMEM  131072
#define G4_SMEM   196608        // new async core: 2 x (A 64K + B 32K)

__device__ __forceinline__ uint32_t pack_bf16x2(float x, float y) {
    uint32_t h;
    asm("cvt.rn.bf16x2.f32 %0, %1, %2;" : "=r"(h) : "f"(y), "f"(x));
    return h;
}
__device__ __forceinline__ void split2(float x, float y, uint32_t& hi, uint32_t& lo) {
    hi = pack_bf16x2(x, y);
    __nv_bfloat162 h2 = *(__nv_bfloat162*)&hi;
    lo = pack_bf16x2(x - __bfloat162float(h2.x), y - __bfloat162float(h2.y));
}
__device__ __forceinline__ void cvt8_store(char* baseH, char* baseL, int r, int g,
                                           float4 v0, float4 v1) {
    uint4 hi, lo;
    split2(v0.x, v0.y, hi.x, lo.x);
    split2(v0.z, v0.w, hi.y, lo.y);
    split2(v1.x, v1.y, hi.z, lo.z);
    split2(v1.z, v1.w, hi.w, lo.w);
    uint32_t off = (uint32_t)(r * 128 + ((g ^ (r & 7)) << 4));
    *(uint4*)(baseH + off) = hi;
    *(uint4*)(baseL + off) = lo;
}

// ---------------- xsplit: fp32 inputs -> presplit bf16 hi/lo (concat) ----------------
// float4 ranges: rgb 1605632 | depth 1605632 | mm 1048576 | lidar 1048576 (all /512 exact)
__global__ __launch_bounds__(512) void xsplit_kernel(
    const float* __restrict__ rgb, const float* __restrict__ depth,
    const float* __restrict__ mmw, const float* __restrict__ lidar)
{
    const size_t idx = (size_t)blockIdx.x * 512 + threadIdx.x;   // float4 index
    const float* src;
    size_t loc = idx;
    if (idx < 1605632)            { src = rgb; }
    else if (idx < 3211264)       { src = depth; loc = idx - 1605632; }
    else if (idx < 4259840)       { src = mmw;   loc = idx - 3211264; }
    else                          { src = lidar; loc = idx - 4259840; }
    float4 v = ((const float4*)src)[loc];
    uint2 hi, lo;
    split2(v.x, v.y, hi.x, lo.x);
    split2(v.z, v.w, hi.y, lo.y);
    ((uint2*)g_xh)[idx] = hi;
    ((uint2*)g_xl)[idx] = lo;
}

// ---------------- gemm4_async: 512 threads, 256x128 tile, fully async ----------------
// C[row, n] = relu((X @ W_z^T)[row,n] * alpha + beta), rows flat-concat (match g_x / g_H)
__global__ __launch_bounds__(512, 1)
void gemm4_async(const float* __restrict__ conv_b,
                 const float* __restrict__ bn_g, const float* __restrict__ bn_b,
                 const float* __restrict__ bn_m, const float* __restrict__ bn_v)
{
    extern __shared__ char smem[];
    __shared__ float s_alpha[128], s_beta[128];

    const int tid = threadIdx.x;
    const int wid = tid >> 5;           // 0..15
    const int lane = tid & 31;
    const int warp_m = wid >> 2;        // 0..3 (64 rows each)
    const int warp_n = wid & 3;         // 0..3 (32 cols each)
    const int y = blockIdx.y;           // 0..161 (256-row tiles)
    const int n0 = blockIdx.x * 128;
    const int z = (y < 49) ? 0 : (y < 98) ? 1 : (y < 130) ? 2 : 3;
    const int row0 = y * 256;           // flat row base (A and C identical)

    if (tid < 128) {
        int c = z * 512 + n0 + tid;
        float s = bn_g[c] * rsqrtf(bn_v[c] + EPS_BN);
        s_alpha[tid] = s;
        s_beta[tid]  = (conv_b[c] - bn_m[c]) * s + bn_b[c];
    }

    float acc[4][4][4];
#pragma unroll
    for (int i = 0; i < 4; i++)
#pragma unroll
        for (int j = 0; j < 4; j++)
#pragma unroll
            for (int q = 0; q < 4; q++) acc[i][j][q] = 0.0f;

    const int g = tid & 7;
    const int rA = tid >> 3;            // 0..63
    const uint32_t sb0 = smem_u32(smem);

#define G4_ISSUE(ck) do {                                                     \
        const int k0 = (ck) << 6;                                             \
        const uint32_t base = sb0 + (uint32_t)(((ck) & 1) * 98304);           \
        _Pragma("unroll")                                                     \
        for (int p = 0; p < 4; p++) {                                         \
            const int r = rA + 64 * p;                                        \
            const uint32_t off = (uint32_t)(r * 128 + ((g ^ (r & 7)) << 4));  \
            const size_t aoff = (size_t)(row0 + r) * 512 + k0 + g * 8;        \
            cp16(base + off, g_xh + aoff);                                    \
            cp16(base + 32768u + off, g_xl + aoff);                           \
        }                                                                     \
        _Pragma("unroll")                                                     \
        for (int p = 0; p < 2; p++) {                                         \
            const int r = rA + 64 * p;                                        \
            const uint32_t off = (uint32_t)(r * 128 + ((g ^ (r & 7)) << 4));  \
            const size_t boff = (size_t)z * 262144 + (size_t)(n0 + r) * 512 + k0 + g * 8; \
            cp16(base + 65536u + off, g_wh + boff);                           \
            cp16(base + 81920u + off, g_wl + boff);                           \
        }                                                                     \
        CP_COMMIT();                                                          \
    } while (0)

    G4_ISSUE(0);
    G4_ISSUE(1);

    for (int ck = 0; ck < 8; ck++) {
        if (ck == 7) { CP_WAIT0(); } else { CP_WAIT1(); }
        __syncthreads();
        {
            const uint32_t abase = sb0 + (uint32_t)((ck & 1) * 98304);
            const uint32_t bbase = abase + 65536u;
            const int arow = warp_m * 64 + (lane & 15);
            const int ahalf = lane >> 4;
            const int bn_ = warp_n * 32 + (lane & 7);
            const int bhalf = (lane >> 3) & 1;
#pragma unroll
            for (int kb = 0; kb < 4; kb++) {
                uint32_t aH[4][4], aL[4][4], bH[4][2], bL[4][2];
#pragma unroll
                for (int mt = 0; mt < 4; mt++) {
                    const int r = arow + mt * 16;
                    const uint32_t chunk = (uint32_t)((2 * kb + ahalf) ^ (r & 7));
                    const uint32_t ad = abase + (uint32_t)(r * 128) + chunk * 16;
                    LDSM_X4(aH[mt][0], aH[mt][1], aH[mt][2], aH[mt][3], ad);
                    LDSM_X4(aL[mt][0], aL[mt][1], aL[mt][2], aL[mt][3], ad + 32768u);
                }
#pragma unroll
                for (int nt = 0; nt < 4; nt++) {
                    const int n = bn_ + nt * 8;
                    const uint32_t chunk = (uint32_t)((2 * kb + bhalf) ^ (n & 7));
                    const uint32_t bd = bbase + (uint32_t)(n * 128) + chunk * 16;
                    LDSM_X2(bH[nt][0], bH[nt][1], bd);
                    LDSM_X2(bL[nt][0], bL[nt][1], bd + TILE_BYTES);
                }
#pragma unroll
                for (int mt = 0; mt < 4; mt++)
#pragma unroll
                    for (int nt = 0; nt < 4; nt++) {
                        mma_bf16(acc[mt][nt], aH[mt], bH[nt]);
                        mma_bf16(acc[mt][nt], aH[mt], bL[nt]);
                        mma_bf16(acc[mt][nt], aL[mt], bH[nt]);
                    }
            }
        }
        __syncthreads();
        if (ck + 2 < 8) G4_ISSUE(ck + 2);
    }
#undef G4_ISSUE

    // epilogue
    const int erow = (lane >> 2);
    const int ecol = 2 * (lane & 3);
#pragma unroll
    for (int mt = 0; mt < 4; mt++) {
#pragma unroll
        for (int nt = 0; nt < 4; nt++) {
            const int lc = warp_n * 32 + nt * 8 + ecol;
            const float a0 = s_alpha[lc], a1 = s_alpha[lc + 1];
            const float b0 = s_beta[lc],  b1 = s_beta[lc + 1];
            const int gr0 = row0 + warp_m * 64 + mt * 16 + erow;
            float* p0 = g_H + (size_t)gr0 * 512 + n0 + lc;
            float* p1 = p0 + (size_t)8 * 512;
            float2 v0, v1;
            v0.x = fmaxf(fmaf(acc[mt][nt][0], a0, b0), 0.0f);
            v0.y = fmaxf(fmaf(acc[mt][nt][1], a1, b1), 0.0f);
            v1.x = fmaxf(fmaf(acc[mt][nt][2], a0, b0), 0.0f);
            v1.y = fmaxf(fmaf(acc[mt][nt][3], a1, b1), 0.0f);
            *(float2*)p0 = v0;
            *(float2*)p1 = v1;
        }
    }
}

// ---------------- old bf16-split core (pe2 only: A generated from xyz) ----------------
__device__ __forceinline__ void gemm_core_pe(
    const __nv_bfloat16* __restrict__ Wh, const __nv_bfloat16* __restrict__ Wl,
    float* __restrict__ C,
    const float* __restrict__ bias,
    const float* __restrict__ bng, const float* __restrict__ bnb,
    const float* __restrict__ bnm, const float* __restrict__ bnv,
    int m0, int n0)
{
    extern __shared__ char smem[];
    __shared__ float s_alpha[128], s_beta[128];

    const int tid = threadIdx.x;
    const int wid = tid >> 5;
    const int lane = tid & 31;
    const int warp_m = wid >> 2;
    const int warp_n = wid & 3;
    const int K = 128;

    if (tid < 128) {
        int c = n0 + tid;
        float s = bng[c] * rsqrtf(bnv[c] + EPS_BN);
        s_alpha[tid] = s;
        s_beta[tid]  = (bias[c] - bnm[c]) * s + bnb[c];
    }

    float acc[4][4][4];
#pragma unroll
    for (int i = 0; i < 4; i++)
#pragma unroll
        for (int j = 0; j < 4; j++)
#pragma unroll
            for (int q = 0; q < 4; q++) acc[i][j][q] = 0.0f;

    const int g = tid & 7;
    const int r0 = tid >> 3;
    const uint32_t sb0 = smem_u32(smem);
    const uint32_t sbB = sb0 + 2u * TILE_BYTES;
    char* AH = smem;
    char* AL = smem + TILE_BYTES;
    const int kn = K >> 6;

#define ISSUE_B(ck) do {                                                      \
        const int bk0 = (ck) << 6;                                            \
        const uint32_t bb = sbB + (uint32_t)(((ck) & 1) << 15);               \
        _Pragma("unroll")                                                     \
        for (int pass = 0; pass < 4; pass++) {                                \
            const int r = r0 + 32 * pass;                                     \
            const size_t woff = (size_t)(n0 + r) * K + bk0 + g * 8;           \
            const uint32_t off = (uint32_t)(r * 128 + ((g ^ (r & 7)) << 4));  \
            cp16(bb + off, Wh + woff);                                        \
            cp16(bb + TILE_BYTES + off, Wl + woff);                           \
        }                                                                     \
        CP_COMMIT();                                                          \
    } while (0)

    ISSUE_B(0);

    for (int ck = 0; ck < kn; ck++) {
        const int k0 = ck << 6;
#pragma unroll
        for (int pass = 0; pass < 4; pass++) {
            const int r = r0 + 32 * pass;
            const float* xyz = g_newxyz + (size_t)(m0 + r) * 3;
            const float px = xyz[0], py = xyz[1], pz = xyz[2];
            float v[8];
#pragma unroll
            for (int q = 0; q < 8; q++) {
                const float* co = g_peA + 4 * (k0 + g * 8 + q);
                v[q] = fmaxf(fmaf(px, co[0], fmaf(py, co[1], fmaf(pz, co[2], co[3]))), 0.0f);
            }
            cvt8_store(AH, AL, r, g, make_float4(v[0], v[1], v[2], v[3]),
                       make_float4(v[4], v[5], v[6], v[7]));
        }
        CP_WAIT0();
        __syncthreads();
        if (ck + 1 < kn) ISSUE_B(ck + 1);

        {
            const uint32_t bbase = sbB + (uint32_t)((ck & 1) << 15);
            const int arow = warp_m * 64 + (lane & 15);
            const int ahalf = lane >> 4;
            const int bn_ = warp_n * 32 + (lane & 7);
            const int bhalf = (lane >> 3) & 1;
#pragma unroll
            for (int kb = 0; kb < 4; kb++) {
                uint32_t aH[4][4], aL[4][4], bH[4][2], bL[4][2];
#pragma unroll
                for (int mt = 0; mt < 4; mt++) {
                    const int r = arow + mt * 16;
                    const uint32_t chunk = (uint32_t)((2 * kb + ahalf) ^ (r & 7));
                    const uint32_t ad = sb0 + (uint32_t)(r * 128) + chunk * 16;
                    LDSM_X4(aH[mt][0], aH[mt][1], aH[mt][2], aH[mt][3], ad);
                    LDSM_X4(aL[mt][0], aL[mt][1], aL[mt][2], aL[mt][3], ad + TILE_BYTES);
                }
#pragma unroll
                for (int nt = 0; nt < 4; nt++) {
                    const int n = bn_ + nt * 8;
                    const uint32_t chunk = (uint32_t)((2 * kb + bhalf) ^ (n & 7));
                    const uint32_t bd = bbase + (uint32_t)(n * 128) + chunk * 16;
                    LDSM_X2(bH[nt][0], bH[nt][1], bd);
                    LDSM_X2(bL[nt][0], bL[nt][1], bd + TILE_BYTES);
                }
#pragma unroll
                for (int mt = 0; mt < 4; mt++)
#pragma unroll
                    for (int nt = 0; nt < 4; nt++) {
                        mma_bf16(acc[mt][nt], aH[mt], bH[nt]);
                        mma_bf16(acc[mt][nt], aH[mt], bL[nt]);
                        mma_bf16(acc[mt][nt], aL[mt], bH[nt]);
                    }
            }
        }
        __syncthreads();
    }
#undef ISSUE_B

    const int erow = (lane >> 2);
    const int ecol = 2 * (lane & 3);
#pragma unroll
    for (int mt = 0; mt < 4; mt++) {
#pragma unroll
        for (int nt = 0; nt < 4; nt++) {
            const int lc = warp_n * 32 + nt * 8 + ecol;
            const float a0 = s_alpha[lc], a1 = s_alpha[lc + 1];
            const float b0 = s_beta[lc],  b1 = s_beta[lc + 1];
            const int gr0 = m0 + warp_m * 64 + mt * 16 + erow;
            float* p0 = C + (size_t)gr0 * 512 + n0 + lc;
            float* p1 = p0 + (size_t)8 * 512;
            float2 v0, v1;
            v0.x = fmaxf(fmaf(acc[mt][nt][0], a0, b0), 0.0f);
            v0.y = fmaxf(fmaf(acc[mt][nt][1], a1, b1), 0.0f);
            v1.x = fmaxf(fmaf(acc[mt][nt][2], a0, b0), 0.0f);
            v1.y = fmaxf(fmaf(acc[mt][nt][3], a1, b1), 0.0f);
            *(float2*)p0 = v0;
            *(float2*)p1 = v1;
        }
    }
}

__global__ __launch_bounds__(256, 2)
void hmma_pe2(const float* __restrict__ bias,
              const float* __restrict__ bng, const float* __restrict__ bnb,
              const float* __restrict__ bnm, const float* __restrict__ bnv)
{
    gemm_core_pe(g_wh + W_PE2_OFF, g_wl + W_PE2_OFF,
                 g_pe, bias, bng, bnb, bnm, bnv,
                 blockIdx.y * 128, blockIdx.x * 128);
}

// ---------------- H row lookup (concat order) ----------------
__device__ __forceinline__ const float* h_row(int lcat, int b, int n0) {
    if (lcat < 49)  return g_H + OFF_RGB   + ((size_t)b * 49 + lcat) * 512 + n0;
    if (lcat < 98)  return g_H + OFF_DEPTH + ((size_t)b * 49 + (lcat - 49)) * 512 + n0;
    if (lcat < 130) return g_H + OFF_MM    + ((size_t)b * 32 + (lcat - 98)) * 512 + n0;
    if (lcat < 162) return g_H + OFF_LIDAR + ((size_t)b * 32 + (lcat - 130)) * 512 + n0;
    return nullptr;
}

// ---------------- transpose: H[b,l,o] -> Ht[b,o,l192] ----------------
__global__ void tp_kernel()
{
    __shared__ unsigned short sH[128 * 34];
    __shared__ unsigned short sL[128 * 34];
    const int tid = threadIdx.x;
    const int obase = blockIdx.x * 128;
    const int lbase = blockIdx.y * 32;
    const int b = blockIdx.z;

    {
        const int o = tid & 127;
        const int half = tid >> 7;
#pragma unroll
        for (int i = 0; i < 16; i++) {
            const int lr = half * 16 + i;
            const float* row = h_row(lbase + lr, b, obase);
            float v = row ? row[o] : 0.0f;
            __nv_bfloat16 h = __float2bfloat16(v);
            __nv_bfloat16 l = __float2bfloat16(v - __bfloat162float(h));
            sH[o * 34 + lr] = __bfloat16_as_ushort(h);
            sL[o * 34 + lr] = __bfloat16_as_ushort(l);
        }
    }
    __syncthreads();
    {
        const int li = tid & 15;
#pragma unroll
        for (int p = 0; p < 8; p++) {
            const int o = p * 16 + (tid >> 4);
            const size_t rowoff = ((size_t)b * 512 + obase + o) * 192 + lbase;
            uint32_t vh = (uint32_t)sH[o * 34 + 2 * li] | ((uint32_t)sH[o * 34 + 2 * li + 1] << 16);
            uint32_t vl = (uint32_t)sL[o * 34 + 2 * li] | ((uint32_t)sL[o * 34 + 2 * li + 1] << 16);
            ((uint32_t*)(g_hth + rowoff))[li] = vh;
            ((uint32_t*)(g_htl + rowoff))[li] = vl;
        }
    }
}

// ---------------- mix GEMM: out = relu(Wblk @ Hcat + lb) + g_pe ----------------
__global__ __launch_bounds__(256, 1)
void mix_gemm(float* __restrict__ out)
{
    extern __shared__ char smem[];
    __shared__ float s_rb[128];

    const int tid = threadIdx.x;
    const int wid = tid >> 5;
    const int lane = tid & 31;
    const int warp_m = wid >> 2;
    const int warp_n = wid & 3;
    const int n0 = blockIdx.x * 128;
    const int b  = blockIdx.y;

    if (tid < 128) s_rb[tid] = g_mlb[tid];

    float acc[4][4][4];
#pragma unroll
    for (int i = 0; i < 4; i++)
#pragma unroll
        for (int j = 0; j < 4; j++)
#pragma unroll
            for (int q = 0; q < 4; q++) acc[i][j][q] = 0.0f;

    const int g = tid & 7;
    const int r0 = tid >> 3;
    const uint32_t sb0 = smem_u32(smem);

#define MIX_ISSUE(ck) do {                                                    \
        const int k0 = (ck) << 6;                                             \
        const uint32_t as = sb0 + (uint32_t)(((ck) & 1) << 15);               \
        const uint32_t bs = sb0 + 65536u + (uint32_t)(((ck) & 1) << 15);      \
        _Pragma("unroll")                                                     \
        for (int pass = 0; pass < 4; pass++) {                                \
            const int r = r0 + 32 * pass;                                     \
            const uint32_t off = (uint32_t)(r * 128 + ((g ^ (r & 7)) << 4));  \
            const size_t aoff = (size_t)r * 192 + k0 + g * 8;                 \
            cp16(as + off, g_mwh + aoff);                                     \
            cp16(as + TILE_BYTES + off, g_mwl + aoff);                        \
            const size_t boff = ((size_t)b * 512 + n0 + r) * 192 + k0 + g * 8;\
            cp16(bs + off, g_hth + boff);                                     \
            cp16(bs + TILE_BYTES + off, g_htl + boff);                        \
        }                                                                     \
        CP_COMMIT();                                                          \
    } while (0)

    MIX_ISSUE(0);
    MIX_ISSUE(1);

    for (int ck = 0; ck < 3; ck++) {
        if (ck == 2) { CP_WAIT0(); } else { CP_WAIT1(); }
        __syncthreads();

        {
            const uint32_t abase = sb0 + (uint32_t)((ck & 1) << 15);
            const uint32_t bbase = sb0 + 65536u + (uint32_t)((ck & 1) << 15);
            const int arow = warp_m * 64 + (lane & 15);
            const int ahalf = lane >> 4;
            const int bn_ = warp_n * 32 + (lane & 7);
            const int bhalf = (lane >> 3) & 1;
#pragma unroll
            for (int kb = 0; kb < 4; kb++) {
                uint32_t aH[4][4], aL[4][4], bH[4][2], bL[4][2];
#pragma unroll
                for (int mt = 0; mt < 4; mt++) {
                    const int r = arow + mt * 16;
                    const uint32_t chunk = (uint32_t)((2 * kb + ahalf) ^ (r & 7));
                    const uint32_t ad = abase + (uint32_t)(r * 128) + chunk * 16;
                    LDSM_X4(aH[mt][0], aH[mt][1], aH[mt][2], aH[mt][3], ad);
                    LDSM_X4(aL[mt][0], aL[mt][1], aL[mt][2], aL[mt][3], ad + TILE_BYTES);
                }
#pragma unroll
                for (int nt = 0; nt < 4; nt++) {
                    const int n = bn_ + nt * 8;
                    const uint32_t chunk = (uint32_t)((2 * kb + bhalf) ^ (n & 7));
                    const uint32_t bd = bbase + (uint32_t)(n * 128) + chunk * 16;
                    LDSM_X2(bH[nt][0], bH[nt][1], bd);
                    LDSM_X2(bL[nt][0], bL[nt][1], bd + TILE_BYTES);
                }
#pragma unroll
                for (int mt = 0; mt < 4; mt++)
#pragma unroll
                    for (int nt = 0; nt < 4; nt++) {
                        mma_bf16(acc[mt][nt], aH[mt], bH[nt]);
                        mma_bf16(acc[mt][nt], aH[mt], bL[nt]);
                        mma_bf16(acc[mt][nt], aL[mt], bH[nt]);
                    }
            }
        }
        __syncthreads();
        if (ck == 0) MIX_ISSUE(2);
    }
#undef MIX_ISSUE

    const int erow = (lane >> 2);
    const int ecol = 2 * (lane & 3);
#pragma unroll
    for (int mt = 0; mt < 4; mt++) {
        const int row = warp_m * 64 + mt * 16 + erow;
        const float rb0 = s_rb[row];
        const float rb1 = s_rb[row + 8];
#pragma unroll
        for (int nt = 0; nt < 4; nt++) {
            const int lc = warp_n * 32 + nt * 8 + ecol;
            const size_t base0 = ((size_t)b * 128 + row) * 512 + n0 + lc;
            const size_t base1 = base0 + (size_t)8 * 512;
            float2 p0 = *(const float2*)(g_pe + base0);
            float2 p1 = *(const float2*)(g_pe + base1);
            float2 v0, v1;
            v0.x = fmaxf(acc[mt][nt][0] + rb0, 0.0f) + p0.x;
            v0.y = fmaxf(acc[mt][nt][1] + rb0, 0.0f) + p0.y;
            v1.x = fmaxf(acc[mt][nt][2] + rb1, 0.0f) + p1.x;
            v1.y = fmaxf(acc[mt][nt][3] + rb1, 0.0f) + p1.y;
            *(float2*)(out + base0) = v0;
            *(float2*)(out + base1) = v1;
        }
    }
}

// ---------------- prep ----------------
__global__ void prep_kernel(const float* __restrict__ conv_w, const float* __restrict__ pe_w2,
                            const float* __restrict__ pe_w1, const float* __restrict__ pe_b1,
                            const float* __restrict__ pe_g1, const float* __restrict__ pe_bb1,
                            const float* __restrict__ pe_m1, const float* __restrict__ pe_v1,
                            const float* __restrict__ lin_w_img, const float* __restrict__ lin_b_img,
                            const float* __restrict__ lin_w_pc,  const float* __restrict__ lin_b_pc)
{
    int idx = blockIdx.x * 256 + threadIdx.x;
    if (idx < W_TOTAL) {
        float v = (idx < W_PE2_OFF) ? conv_w[idx] : pe_w2[idx - W_PE2_OFF];
        __nv_bfloat16 h = __float2bfloat16(v);
        g_wh[idx] = h;
        g_wl[idx] = __float2bfloat16(v - __bfloat162float(h));
    }
    if (idx < 128 * 192) {
        const int krow = idx / 192, lcat = idx % 192;
        const int mod = krow >> 5, k = krow & 31;
        float w = 0.0f;
        if (mod == 0)      { if (lcat < 49)                 w = lin_w_img[k * 49 + lcat]; }
        else if (mod == 1) { if (lcat >= 49 && lcat < 98)   w = lin_w_img[(32 + k) * 49 + lcat - 49]; }
        else if (mod == 2) { if (lcat >= 98 && lcat < 130)  w = lin_w_pc[k * 32 + lcat - 98]; }
        else               { if (lcat >= 130 && lcat < 162) w = lin_w_pc[(32 + k) * 32 + lcat - 130]; }
        __nv_bfloat16 h = __float2bfloat16(w);
        g_mwh[idx] = h;
        g_mwl[idx] = __float2bfloat16(w - __bfloat162float(h));
    }
    if (idx < 128) {
        const int mod = idx >> 5, k = idx & 31;
        g_mlb[idx] = (mod == 0) ? lin_b_img[k] : (mod == 1) ? lin_b_img[32 + k]
                   : (mod == 2) ? lin_b_pc[k] : lin_b_pc[32 + k];
        float s = pe_g1[idx] * rsqrtf(pe_v1[idx] + EPS_BN);
        g_peA[idx * 4 + 0] = pe_w1[idx * 3 + 0] * s;
        g_peA[idx * 4 + 1] = pe_w1[idx * 3 + 1] * s;
        g_peA[idx * 4 + 2] = pe_w1[idx * 3 + 2] * s;
        g_peA[idx * 4 + 3] = (pe_b1[idx] - pe_m1[idx]) * s + pe_bb1[idx];
    }
}

// ---------------- threefry / FPS ----------------
__device__ __forceinline__ unsigned rotl32(unsigned x, int d) {
    return (x << d) | (x >> (32 - d));
}
#define TF_ROUND(x0, x1, r) do { x0 += x1; x1 = rotl32(x1, r); x1 ^= x0; } while (0)
__device__ __forceinline__ void threefry2x32(unsigned k0, unsigned k1,
                                             unsigned& x0, unsigned& x1) {
    const unsigned kx = 0x1BD11BDAu ^ k0 ^ k1;
    x0 += k0; x1 += k1;
    TF_ROUND(x0, x1, 13); TF_ROUND(x0, x1, 15); TF_ROUND(x0, x1, 26); TF_ROUND(x0, x1, 6);
    x0 += k1; x1 += kx + 1u;
    TF_ROUND(x0, x1, 17); TF_ROUND(x0, x1, 29); TF_ROUND(x0, x1, 16); TF_ROUND(x0, x1, 24);
    x0 += kx; x1 += k0 + 2u;
    TF_ROUND(x0, x1, 13); TF_ROUND(x0, x1, 15); TF_ROUND(x0, x1, 26); TF_ROUND(x0, x1, 6);
    x0 += k0; x1 += k1 + 3u;
    TF_ROUND(x0, x1, 17); TF_ROUND(x0, x1, 29); TF_ROUND(x0, x1, 16); TF_ROUND(x0, x1, 24);
    x0 += k1; x1 += kx + 4u;
    TF_ROUND(x0, x1, 13); TF_ROUND(x0, x1, 15); TF_ROUND(x0, x1, 26); TF_ROUND(x0, x1, 6);
    x0 += kx; x1 += k0 + 5u;
}
__device__ __forceinline__ uint32_t redux_max_u32(uint32_t v) {
    uint32_t r;
    asm("redux.sync.max.u32 %0, %1, 0xffffffff;" : "=r"(r) : "r"(v));
    return r;
}
__device__ __forceinline__ uint32_t redux_min_u32(uint32_t v) {
    uint32_t r;
    asm("redux.sync.min.u32 %0, %1, 0xffffffff;" : "=r"(r) : "r"(v));
    return r;
}

__global__ __launch_bounds__(512)
void fps_kernel(const float* __restrict__ pts, float* __restrict__ nxyz) {
    extern __shared__ float sh[];
    float* xs = sh;
    float* ys = sh + 4096;
    float* zs = sh + 8192;
    __shared__ uint32_t red_v[16];
    __shared__ uint32_t red_i[16];
    __shared__ int sm_far;

    const int b = blockIdx.x;
    const int tid = threadIdx.x;
    const int lane = tid & 31;
    const int warp = tid >> 5;
    const float* p = pts + (size_t)b * 4096 * 3;
    for (int i = tid; i < 4096; i += 512) {
        xs[i] = p[3 * i + 0];
        ys[i] = p[3 * i + 1];
        zs[i] = p[3 * i + 2];
    }
    if (tid == 0) {
        unsigned a0 = 0u, a1 = 1u;
        threefry2x32(0u, 42u, a0, a1);
        unsigned c0 = 0u, c1 = (unsigned)b;
        threefry2x32(a0, a1, c0, c1);
        sm_far = (int)((c0 ^ c1) & 4095u);
    }
    __syncthreads();

    float dist[8];
#pragma unroll
    for (int j = 0; j < 8; j++) dist[j] = 1e10f;

    float* outp = nxyz + (size_t)b * 128 * 3;
    for (int it = 0; it < 128; ++it) {
        const int far = sm_far;
        const float cx = xs[far], cy = ys[far], cz = zs[far];
        if (tid == 0) {
            outp[3 * it + 0] = cx;
            outp[3 * it + 1] = cy;
            outp[3 * it + 2] = cz;
        }
        float bv = -1.0f;
        int bi = 0;
#pragma unroll
        for (int j = 0; j < 8; j++) {
            const int pi = (j << 9) + tid;
            float dx = __fadd_rn(xs[pi], -cx);
            float dy = __fadd_rn(ys[pi], -cy);
            float dz = __fadd_rn(zs[pi], -cz);
            float s0 = __fmul_rn(dx, dx);
            float s1 = __fmul_rn(dy, dy);
            float s2 = __fmul_rn(dz, dz);
            float d  = __fadd_rn(__fadd_rn(s0, s1), s2);
            float nd = fminf(dist[j], d);
            dist[j] = nd;
            if (nd > bv) { bv = nd; bi = pi; }
        }
        uint32_t bvu = __float_as_uint(bv);
        uint32_t gv = redux_max_u32(bvu);
        uint32_t cand = (bvu == gv) ? (uint32_t)bi : 0xFFFFFFFFu;
        uint32_t gi = redux_min_u32(cand);
        if (lane == 0) { red_v[warp] = gv; red_i[warp] = gi; }
        __syncthreads();
        if (tid < 32) {
            uint32_t v = (lane < 16) ? red_v[lane] : 0u;
            uint32_t i = (lane < 16) ? red_i[lane] : 0xFFFFFFFFu;
            uint32_t gv2 = redux_max_u32(v);
            uint32_t cand2 = (v == gv2) ? i : 0xFFFFFFFFu;
            uint32_t gi2 = redux_min_u32(cand2);
            if (lane == 0) sm_far = (int)gi2;
        }
        __syncthreads();
    }
}

// ---------------- launch ----------------
extern "C" void kernel_launch(void* const* d_in, const int* in_sizes, int n_in,
                              void* d_out, int out_size) {
    (void)in_sizes; (void)n_in; (void)out_size;
    const float* rgb       = (const float*)d_in[0];
    const float* depth     = (const float*)d_in[1];
    const float* mmwave    = (const float*)d_in[2];
    const float* lidar     = (const float*)d_in[3];
    const float* pts       = (const float*)d_in[4];
    const float* conv_w    = (const float*)d_in[5];
    const float* conv_b    = (const float*)d_in[6];
    const float* bn_g      = (const float*)d_in[7];
    const float* bn_b      = (const float*)d_in[8];
    const float* bn_m      = (const float*)d_in[9];
    const float* bn_v      = (const float*)d_in[10];
    const float* lin_w_img = (const float*)d_in[11];
    const float* lin_b_img = (const float*)d_in[12];
    const float* lin_w_pc  = (const float*)d_in[13];
    const float* lin_b_pc  = (const float*)d_in[14];
    const float* pe_w1     = (const float*)d_in[15];
    const float* pe_b1     = (const float*)d_in[16];
    const float* pe_g1     = (const float*)d_in[17];
    const float* pe_bb1    = (const float*)d_in[18];
    const float* pe_m1     = (const float*)d_in[19];
    const float* pe_v1     = (const float*)d_in[20];
    const float* pe_w2     = (const float*)d_in[21];
    const float* pe_b2     = (const float*)d_in[22];
    const float* pe_g2     = (const float*)d_in[23];
    const float* pe_bb2    = (const float*)d_in[24];
    const float* pe_m2     = (const float*)d_in[25];
    const float* pe_v2     = (const float*)d_in[26];
    float* out = (float*)d_out;

    float* nx;
    cudaGetSymbolAddress((void**)&nx, g_newxyz);

    static cudaStream_t s2 = nullptr;
    static cudaEvent_t evA = nullptr, evP = nullptr, evB = nullptr;
    if (!s2) {
        cudaStreamCreateWithFlags(&s2, cudaStreamNonBlocking);
        cudaEventCreateWithFlags(&evA, cudaEventDisableTiming);
        cudaEventCreateWithFlags(&evP, cudaEventDisableTiming);
        cudaEventCreateWithFlags(&evB, cudaEventDisableTiming);
        cudaFuncSetAttribute(fps_kernel, cudaFuncAttributeMaxDynamicSharedMemorySize, 50176);
        cudaFuncSetAttribute(gemm4_async, cudaFuncAttributeMaxDynamicSharedMemorySize, G4_SMEM);
        cudaFuncSetAttribute(hmma_pe2, cudaFuncAttributeMaxDynamicSharedMemorySize, GEMM_SMEM);
        cudaFuncSetAttribute(mix_gemm, cudaFuncAttributeMaxDynamicSharedMemorySize, MIX_SMEM);
    }

    // fork: FPS on side stream
    cudaEventRecord(evA, 0);
    cudaStreamWaitEvent(s2, evA, 0);
    fps_kernel<<<256, 512, 49152, s2>>>(pts, nx);

    // main: prep then xsplit
    prep_kernel<<<(W_TOTAL + 255) / 256, 256>>>(conv_w, pe_w2, pe_w1, pe_b1,
                                                pe_g1, pe_bb1, pe_m1, pe_v1,
                                                lin_w_img, lin_b_img, lin_w_pc, lin_b_pc);
    cudaEventRecord(evP, 0);
    xsplit_kernel<<<10368, 512>>>(rgb, depth, mmwave, lidar);

    // side: pe2 (needs FPS + prep) -> g_pe
    cudaStreamWaitEvent(s2, evP, 0);
    hmma_pe2<<<dim3(4, 256), 256, GEMM_SMEM, s2>>>(pe_b2, pe_g2, pe_bb2, pe_m2, pe_v2);
    cudaEventRecord(evB, s2);

    // main: branch GEMMs -> transpose -> mix (+pe add fused)
    gemm4_async<<<dim3(4, 162), 512, G4_SMEM>>>(conv_b, bn_g, bn_b, bn_m, bn_v);
    tp_kernel<<<dim3(4, 6, 256), 256>>>();
    cudaStreamWaitEvent(0, evB, 0);
    mix_gemm<<<dim3(4, 256), 256, MIX_SMEM>>>(out);
}

// round 16
// speedup vs baseline: 1.1443x; 1.1443x over previous
#include <cuda_runtime.h>
#include <cuda_bf16.h>
#include <math.h>
#include <stdint.h>

#define EPS_BN 1e-5f

// ---------------- scratch ----------------
__device__ float g_newxyz[256 * 128 * 3];
__device__ float g_pe[16777216];                 // pe2 relu-term [B*128, 512]

// pre-split activations X (concat rgb|depth|mm|lidar), [41472, 512] bf16 hi/lo
__device__ __nv_bfloat16 g_xh[21233664];
__device__ __nv_bfloat16 g_xl[21233664];
// pre-split H output of branch GEMMs, natural layout [41472, 512] bf16 hi/lo
__device__ __nv_bfloat16 g_hh[21233664];
__device__ __nv_bfloat16 g_hl[21233664];

// pre-split weights (hi/lo bf16)
#define W_PE2_OFF (4 * 512 * 512)
#define W_TOTAL   (4 * 512 * 512 + 512 * 128)
__device__ __nv_bfloat16 g_wh[W_TOTAL];
__device__ __nv_bfloat16 g_wl[W_TOTAL];
// folded pos-enc layer1 coeffs
__device__ float g_peA[128 * 4];
// block-diagonal mix weight [128, 192] bf16 hi/lo + row bias
__device__ __nv_bfloat16 g_mwh[128 * 192];
__device__ __nv_bfloat16 g_mwl[128 * 192];
__device__ float g_mlb[128];

// ---------------- helpers ----------------
__device__ __forceinline__ uint32_t smem_u32(const void* p) {
    uint32_t a;
    asm("{ .reg .u64 t; cvta.to.shared.u64 t, %1; cvt.u32.u64 %0, t; }" : "=r"(a) : "l"(p));
    return a;
}
__device__ __forceinline__ void cp16(uint32_t dst, const void* src) {
    asm volatile("cp.async.cg.shared.global [%0], [%1], 16;" :: "r"(dst), "l"(src));
}
__device__ __forceinline__ void cp16z(uint32_t dst, const void* src, uint32_t sz) {
    asm volatile("cp.async.cg.shared.global [%0], [%1], 16, %2;" :: "r"(dst), "l"(src), "r"(sz));
}
#define CP_COMMIT() asm volatile("cp.async.commit_group;" ::: "memory")
#define CP_WAIT0()  asm volatile("cp.async.wait_group 0;" ::: "memory")
#define CP_WAIT1()  asm volatile("cp.async.wait_group 1;" ::: "memory")

__device__ __forceinline__ void mma_bf16(float* c, const uint32_t* a, const uint32_t* b) {
    asm volatile(
        "mma.sync.aligned.m16n8k16.row.col.f32.bf16.bf16.f32 "
        "{%0,%1,%2,%3}, {%4,%5,%6,%7}, {%8,%9}, {%0,%1,%2,%3};"
        : "+f"(c[0]), "+f"(c[1]), "+f"(c[2]), "+f"(c[3])
        : "r"(a[0]), "r"(a[1]), "r"(a[2]), "r"(a[3]), "r"(b[0]), "r"(b[1]));
}
#define LDSM_X4(r0, r1, r2, r3, addr)                                        \
    asm volatile("ldmatrix.sync.aligned.m8n8.x4.shared.b16 {%0,%1,%2,%3}, [%4];" \
                 : "=r"(r0), "=r"(r1), "=r"(r2), "=r"(r3) : "r"(addr))
#define LDSM_X2(r0, r1, addr)                                                \
    asm volatile("ldmatrix.sync.aligned.m8n8.x2.shared.b16 {%0,%1}, [%2];"   \
                 : "=r"(r0), "=r"(r1) : "r"(addr))
#define LDSM_X2_T(r0, r1, addr)                                              \
    asm volatile("ldmatrix.sync.aligned.m8n8.x2.trans.shared.b16 {%0,%1}, [%2];" \
                 : "=r"(r0), "=r"(r1) : "r"(addr))

#define TILE_BYTES 16384
#define GEMM_SMEM 98304         // pe2 core
#define MIX_SMEM  131072        // 2 stages x (A 32K + B 32K)
#define G4_SMEM   196608        // 2 x (A 64K + B 32K)

__device__ __forceinline__ uint32_t pack_bf16x2(float x, float y) {
    uint32_t h;
    asm("cvt.rn.bf16x2.f32 %0, %1, %2;" : "=r"(h) : "f"(y), "f"(x));
    return h;
}
__device__ __forceinline__ void split2(float x, float y, uint32_t& hi, uint32_t& lo) {
    hi = pack_bf16x2(x, y);
    __nv_bfloat162 h2 = *(__nv_bfloat162*)&hi;
    lo = pack_bf16x2(x - __bfloat162float(h2.x), y - __bfloat162float(h2.y));
}
__device__ __forceinline__ void cvt8_store(char* baseH, char* baseL, int r, int g,
                                           float4 v0, float4 v1) {
    uint4 hi, lo;
    split2(v0.x, v0.y, hi.x, lo.x);
    split2(v0.z, v0.w, hi.y, lo.y);
    split2(v1.x, v1.y, hi.z, lo.z);
    split2(v1.z, v1.w, hi.w, lo.w);
    uint32_t off = (uint32_t)(r * 128 + ((g ^ (r & 7)) << 4));
    *(uint4*)(baseH + off) = hi;
    *(uint4*)(baseL + off) = lo;
}

// flat H row for concat token lcat in batch b (-1 = pad)
__device__ __forceinline__ int h_flat_row(int lcat, int b) {
    if (lcat < 49)  return b * 49 + lcat;
    if (lcat < 98)  return 12544 + b * 49 + (lcat - 49);
    if (lcat < 130) return 25088 + b * 32 + (lcat - 98);
    if (lcat < 162) return 33280 + b * 32 + (lcat - 130);
    return -1;
}

// ---------------- xsplit: fp32 inputs -> presplit bf16 hi/lo (concat) ----------------
__global__ __launch_bounds__(512) void xsplit_kernel(
    const float* __restrict__ rgb, const float* __restrict__ depth,
    const float* __restrict__ mmw, const float* __restrict__ lidar)
{
    const size_t idx = (size_t)blockIdx.x * 512 + threadIdx.x;   // float4 index
    const float* src;
    size_t loc = idx;
    if (idx < 1605632)            { src = rgb; }
    else if (idx < 3211264)       { src = depth; loc = idx - 1605632; }
    else if (idx < 4259840)       { src = mmw;   loc = idx - 3211264; }
    else                          { src = lidar; loc = idx - 4259840; }
    float4 v = ((const float4*)src)[loc];
    uint2 hi, lo;
    split2(v.x, v.y, hi.x, lo.x);
    split2(v.z, v.w, hi.y, lo.y);
    ((uint2*)g_xh)[idx] = hi;
    ((uint2*)g_xl)[idx] = lo;
}

// ---------------- gemm4_async: 512 threads, 256x128 tile; H written presplit ----------------
__global__ __launch_bounds__(512, 1)
void gemm4_async(const float* __restrict__ conv_b,
                 const float* __restrict__ bn_g, const float* __restrict__ bn_b,
                 const float* __restrict__ bn_m, const float* __restrict__ bn_v)
{
    extern __shared__ char smem[];
    __shared__ float s_alpha[128], s_beta[128];

    const int tid = threadIdx.x;
    const int wid = tid >> 5;
    const int lane = tid & 31;
    const int warp_m = wid >> 2;        // 0..3
    const int warp_n = wid & 3;         // 0..3
    const int y = blockIdx.y;           // 0..161
    const int n0 = blockIdx.x * 128;
    const int z = (y < 49) ? 0 : (y < 98) ? 1 : (y < 130) ? 2 : 3;
    const int row0 = y * 256;

    if (tid < 128) {
        int c = z * 512 + n0 + tid;
        float s = bn_g[c] * rsqrtf(bn_v[c] + EPS_BN);
        s_alpha[tid] = s;
        s_beta[tid]  = (conv_b[c] - bn_m[c]) * s + bn_b[c];
    }

    float acc[4][4][4];
#pragma unroll
    for (int i = 0; i < 4; i++)
#pragma unroll
        for (int j = 0; j < 4; j++)
#pragma unroll
            for (int q = 0; q < 4; q++) acc[i][j][q] = 0.0f;

    const int g = tid & 7;
    const int rA = tid >> 3;            // 0..63
    const uint32_t sb0 = smem_u32(smem);

#define G4_ISSUE(ck) do {                                                     \
        const int k0 = (ck) << 6;                                             \
        const uint32_t base = sb0 + (uint32_t)(((ck) & 1) * 98304);           \
        _Pragma("unroll")                                                     \
        for (int p = 0; p < 4; p++) {                                         \
            const int r = rA + 64 * p;                                        \
            const uint32_t off = (uint32_t)(r * 128 + ((g ^ (r & 7)) << 4));  \
            const size_t aoff = (size_t)(row0 + r) * 512 + k0 + g * 8;        \
            cp16(base + off, g_xh + aoff);                                    \
            cp16(base + 32768u + off, g_xl + aoff);                           \
        }                                                                     \
        _Pragma("unroll")                                                     \
        for (int p = 0; p < 2; p++) {                                         \
            const int r = rA + 64 * p;                                        \
            const uint32_t off = (uint32_t)(r * 128 + ((g ^ (r & 7)) << 4));  \
            const size_t boff = (size_t)z * 262144 + (size_t)(n0 + r) * 512 + k0 + g * 8; \
            cp16(base + 65536u + off, g_wh + boff);                           \
            cp16(base + 81920u + off, g_wl + boff);                           \
        }                                                                     \
        CP_COMMIT();                                                          \
    } while (0)

    G4_ISSUE(0);
    G4_ISSUE(1);

    for (int ck = 0; ck < 8; ck++) {
        if (ck == 7) { CP_WAIT0(); } else { CP_WAIT1(); }
        __syncthreads();
        {
            const uint32_t abase = sb0 + (uint32_t)((ck & 1) * 98304);
            const uint32_t bbase = abase + 65536u;
            const int arow = warp_m * 64 + (lane & 15);
            const int ahalf = lane >> 4;
            const int bn_ = warp_n * 32 + (lane & 7);
            const int bhalf = (lane >> 3) & 1;
#pragma unroll
            for (int kb = 0; kb < 4; kb++) {
                uint32_t aH[4][4], aL[4][4], bH[4][2], bL[4][2];
#pragma unroll
                for (int mt = 0; mt < 4; mt++) {
                    const int r = arow + mt * 16;
                    const uint32_t chunk = (uint32_t)((2 * kb + ahalf) ^ (r & 7));
                    const uint32_t ad = abase + (uint32_t)(r * 128) + chunk * 16;
                    LDSM_X4(aH[mt][0], aH[mt][1], aH[mt][2], aH[mt][3], ad);
                    LDSM_X4(aL[mt][0], aL[mt][1], aL[mt][2], aL[mt][3], ad + 32768u);
                }
#pragma unroll
                for (int nt = 0; nt < 4; nt++) {
                    const int n = bn_ + nt * 8;
                    const uint32_t chunk = (uint32_t)((2 * kb + bhalf) ^ (n & 7));
                    const uint32_t bd = bbase + (uint32_t)(n * 128) + chunk * 16;
                    LDSM_X2(bH[nt][0], bH[nt][1], bd);
                    LDSM_X2(bL[nt][0], bL[nt][1], bd + TILE_BYTES);
                }
#pragma unroll
                for (int mt = 0; mt < 4; mt++)
#pragma unroll
                    for (int nt = 0; nt < 4; nt++) {
                        mma_bf16(acc[mt][nt], aH[mt], bH[nt]);
                        mma_bf16(acc[mt][nt], aH[mt], bL[nt]);
                        mma_bf16(acc[mt][nt], aL[mt], bH[nt]);
                    }
            }
        }
        __syncthreads();
        if (ck + 2 < 8) G4_ISSUE(ck + 2);
    }
#undef G4_ISSUE

    // epilogue: bn+relu, split to bf16 hi/lo, packed uint32 stores (natural layout)
    const int erow = (lane >> 2);
    const int ecol = 2 * (lane & 3);
    uint32_t* hh32 = (uint32_t*)g_hh;
    uint32_t* hl32 = (uint32_t*)g_hl;
#pragma unroll
    for (int mt = 0; mt < 4; mt++) {
#pragma unroll
        for (int nt = 0; nt < 4; nt++) {
            const int lc = warp_n * 32 + nt * 8 + ecol;
            const float a0 = s_alpha[lc], a1 = s_alpha[lc + 1];
            const float b0 = s_beta[lc],  b1 = s_beta[lc + 1];
            const int gr0 = row0 + warp_m * 64 + mt * 16 + erow;
            float v00 = fmaxf(fmaf(acc[mt][nt][0], a0, b0), 0.0f);
            float v01 = fmaxf(fmaf(acc[mt][nt][1], a1, b1), 0.0f);
            float v10 = fmaxf(fmaf(acc[mt][nt][2], a0, b0), 0.0f);
            float v11 = fmaxf(fmaf(acc[mt][nt][3], a1, b1), 0.0f);
            uint32_t h0, l0, h1, l1;
            split2(v00, v01, h0, l0);
            split2(v10, v11, h1, l1);
            const size_t i0 = ((size_t)gr0 * 512 + n0 + lc) >> 1;
            const size_t i1 = i0 + 8 * 256;
            hh32[i0] = h0; hl32[i0] = l0;
            hh32[i1] = h1; hl32[i1] = l1;
        }
    }
}

// ---------------- pe2 core (A generated from xyz) ----------------
__device__ __forceinline__ void gemm_core_pe(
    const __nv_bfloat16* __restrict__ Wh, const __nv_bfloat16* __restrict__ Wl,
    float* __restrict__ C,
    const float* __restrict__ bias,
    const float* __restrict__ bng, const float* __restrict__ bnb,
    const float* __restrict__ bnm, const float* __restrict__ bnv,
    int m0, int n0)
{
    extern __shared__ char smem[];
    __shared__ float s_alpha[128], s_beta[128];

    const int tid = threadIdx.x;
    const int wid = tid >> 5;
    const int lane = tid & 31;
    const int warp_m = wid >> 2;
    const int warp_n = wid & 3;
    const int K = 128;

    if (tid < 128) {
        int c = n0 + tid;
        float s = bng[c] * rsqrtf(bnv[c] + EPS_BN);
        s_alpha[tid] = s;
        s_beta[tid]  = (bias[c] - bnm[c]) * s + bnb[c];
    }

    float acc[4][4][4];
#pragma unroll
    for (int i = 0; i < 4; i++)
#pragma unroll
        for (int j = 0; j < 4; j++)
#pragma unroll
            for (int q = 0; q < 4; q++) acc[i][j][q] = 0.0f;

    const int g = tid & 7;
    const int r0 = tid >> 3;
    const uint32_t sb0 = smem_u32(smem);
    const uint32_t sbB = sb0 + 2u * TILE_BYTES;
    char* AH = smem;
    char* AL = smem + TILE_BYTES;
    const int kn = K >> 6;

#define ISSUE_B(ck) do {                                                      \
        const int bk0 = (ck) << 6;                                            \
        const uint32_t bb = sbB + (uint32_t)(((ck) & 1) << 15);               \
        _Pragma("unroll")                                                     \
        for (int pass = 0; pass < 4; pass++) {                                \
            const int r = r0 + 32 * pass;                                     \
            const size_t woff = (size_t)(n0 + r) * K + bk0 + g * 8;           \
            const uint32_t off = (uint32_t)(r * 128 + ((g ^ (r & 7)) << 4));  \
            cp16(bb + off, Wh + woff);                                        \
            cp16(bb + TILE_BYTES + off, Wl + woff);                           \
        }                                                                     \
        CP_COMMIT();                                                          \
    } while (0)

    ISSUE_B(0);

    for (int ck = 0; ck < kn; ck++) {
        const int k0 = ck << 6;
#pragma unroll
        for (int pass = 0; pass < 4; pass++) {
            const int r = r0 + 32 * pass;
            const float* xyz = g_newxyz + (size_t)(m0 + r) * 3;
            const float px = xyz[0], py = xyz[1], pz = xyz[2];
            float v[8];
#pragma unroll
            for (int q = 0; q < 8; q++) {
                const float* co = g_peA + 4 * (k0 + g * 8 + q);
                v[q] = fmaxf(fmaf(px, co[0], fmaf(py, co[1], fmaf(pz, co[2], co[3]))), 0.0f);
            }
            cvt8_store(AH, AL, r, g, make_float4(v[0], v[1], v[2], v[3]),
                       make_float4(v[4], v[5], v[6], v[7]));
        }
        CP_WAIT0();
        __syncthreads();
        if (ck + 1 < kn) ISSUE_B(ck + 1);

        {
            const uint32_t bbase = sbB + (uint32_t)((ck & 1) << 15);
            const int arow = warp_m * 64 + (lane & 15);
            const int ahalf = lane >> 4;
            const int bn_ = warp_n * 32 + (lane & 7);
            const int bhalf = (lane >> 3) & 1;
#pragma unroll
            for (int kb = 0; kb < 4; kb++) {
                uint32_t aH[4][4], aL[4][4], bH[4][2], bL[4][2];
#pragma unroll
                for (int mt = 0; mt < 4; mt++) {
                    const int r = arow + mt * 16;
                    const uint32_t chunk = (uint32_t)((2 * kb + ahalf) ^ (r & 7));
                    const uint32_t ad = sb0 + (uint32_t)(r * 128) + chunk * 16;
                    LDSM_X4(aH[mt][0], aH[mt][1], aH[mt][2], aH[mt][3], ad);
                    LDSM_X4(aL[mt][0], aL[mt][1], aL[mt][2], aL[mt][3], ad + TILE_BYTES);
                }
#pragma unroll
                for (int nt = 0; nt < 4; nt++) {
                    const int n = bn_ + nt * 8;
                    const uint32_t chunk = (uint32_t)((2 * kb + bhalf) ^ (n & 7));
                    const uint32_t bd = bbase + (uint32_t)(n * 128) + chunk * 16;
                    LDSM_X2(bH[nt][0], bH[nt][1], bd);
                    LDSM_X2(bL[nt][0], bL[nt][1], bd + TILE_BYTES);
                }
#pragma unroll
                for (int mt = 0; mt < 4; mt++)
#pragma unroll
                    for (int nt = 0; nt < 4; nt++) {
                        mma_bf16(acc[mt][nt], aH[mt], bH[nt]);
                        mma_bf16(acc[mt][nt], aH[mt], bL[nt]);
                        mma_bf16(acc[mt][nt], aL[mt], bH[nt]);
                    }
            }
        }
        __syncthreads();
    }
#undef ISSUE_B

    const int erow = (lane >> 2);
    const int ecol = 2 * (lane & 3);
#pragma unroll
    for (int mt = 0; mt < 4; mt++) {
#pragma unroll
        for (int nt = 0; nt < 4; nt++) {
            const int lc = warp_n * 32 + nt * 8 + ecol;
            const float a0 = s_alpha[lc], a1 = s_alpha[lc + 1];
            const float b0 = s_beta[lc],  b1 = s_beta[lc + 1];
            const int gr0 = m0 + warp_m * 64 + mt * 16 + erow;
            float* p0 = C + (size_t)gr0 * 512 + n0 + lc;
            float* p1 = p0 + (size_t)8 * 512;
            float2 v0, v1;
            v0.x = fmaxf(fmaf(acc[mt][nt][0], a0, b0), 0.0f);
            v0.y = fmaxf(fmaf(acc[mt][nt][1], a1, b1), 0.0f);
            v1.x = fmaxf(fmaf(acc[mt][nt][2], a0, b0), 0.0f);
            v1.y = fmaxf(fmaf(acc[mt][nt][3], a1, b1), 0.0f);
            *(float2*)p0 = v0;
            *(float2*)p1 = v1;
        }
    }
}

__global__ __launch_bounds__(256, 2)
void hmma_pe2(const float* __restrict__ bias,
              const float* __restrict__ bng, const float* __restrict__ bnb,
              const float* __restrict__ bnm, const float* __restrict__ bnv)
{
    gemm_core_pe(g_wh + W_PE2_OFF, g_wl + W_PE2_OFF,
                 g_pe, bias, bng, bnb, bnm, bnv,
                 blockIdx.y * 128, blockIdx.x * 128);
}

// ---------------- mix GEMM: out = relu(Wblk @ Hcat + lb) + g_pe ----------------
// A = Wblk[128,192] presplit. B = H natural layout via ldmatrix.trans.
// smem stage: A_hi 16K | A_lo 16K | B_hi 16K | B_lo 16K  (x2 stages)
__global__ __launch_bounds__(256, 1)
void mix_gemm(float* __restrict__ out)
{
    extern __shared__ char smem[];
    __shared__ float s_rb[128];

    const int tid = threadIdx.x;
    const int wid = tid >> 5;
    const int lane = tid & 31;
    const int warp_m = wid >> 2;
    const int warp_n = wid & 3;
    const int n0 = blockIdx.x * 128;
    const int b  = blockIdx.y;

    if (tid < 128) s_rb[tid] = g_mlb[tid];

    float acc[4][4][4];
#pragma unroll
    for (int i = 0; i < 4; i++)
#pragma unroll
        for (int j = 0; j < 4; j++)
#pragma unroll
            for (int q = 0; q < 4; q++) acc[i][j][q] = 0.0f;

    const uint32_t sb0 = smem_u32(smem);

#define MIX_ISSUE(ck) do {                                                    \
        const int k0 = (ck) << 6;                                             \
        const uint32_t st = sb0 + (uint32_t)(((ck) & 1) << 16);               \
        {   /* A: Wblk rows 128 x 64 l */                                     \
            const int g = tid & 7;                                            \
            const int r0 = tid >> 3;                                          \
            _Pragma("unroll")                                                 \
            for (int pass = 0; pass < 4; pass++) {                            \
                const int r = r0 + 32 * pass;                                 \
                const uint32_t off = (uint32_t)(r * 128 + ((g ^ (r & 7)) << 4)); \
                const size_t aoff = (size_t)r * 192 + k0 + g * 8;             \
                cp16(st + off, g_mwh + aoff);                                 \
                cp16(st + 16384u + off, g_mwl + aoff);                        \
            }                                                                 \
        }                                                                     \
        {   /* B: H rows (l) x 128 o, 256B rows */                            \
            const int r = tid >> 2;                                           \
            const int jb = (tid & 3) * 4;                                     \
            int fr = h_flat_row(k0 + r, b);                                   \
            uint32_t sz = 16;                                                 \
            if (fr < 0) { fr = 0; sz = 0; }                                   \
            const size_t srcbase = (size_t)fr * 512 + n0;                     \
            _Pragma("unroll")                                                 \
            for (int j = 0; j < 4; j++) {                                     \
                const int oc = jb + j;                                        \
                const uint32_t off = (uint32_t)(r * 256 + ((oc ^ (r & 7)) << 4)); \
                cp16z(st + 32768u + off, g_hh + srcbase + oc * 8, sz);        \
                cp16z(st + 49152u + off, g_hl + srcbase + oc * 8, sz);        \
            }                                                                 \
        }                                                                     \
        CP_COMMIT();                                                          \
    } while (0)

    MIX_ISSUE(0);
    MIX_ISSUE(1);

    for (int ck = 0; ck < 3; ck++) {
        if (ck == 2) { CP_WAIT0(); } else { CP_WAIT1(); }
        __syncthreads();

        {
            const uint32_t abase = sb0 + (uint32_t)((ck & 1) << 16);
            const uint32_t bbase = abase + 32768u;
            const int arow = warp_m * 64 + (lane & 15);
            const int ahalf = lane >> 4;
            const int rl16 = lane & 15;          // trans-B lane row within k16
#pragma unroll
            for (int kb = 0; kb < 4; kb++) {
                uint32_t aH[4][4], aL[4][4], bH[4][2], bL[4][2];
#pragma unroll
                for (int mt = 0; mt < 4; mt++) {
                    const int r = arow + mt * 16;
                    const uint32_t chunk = (uint32_t)((2 * kb + ahalf) ^ (r & 7));
                    const uint32_t ad = abase + (uint32_t)(r * 128) + chunk * 16;
                    LDSM_X4(aH[mt][0], aH[mt][1], aH[mt][2], aH[mt][3], ad);
                    LDSM_X4(aL[mt][0], aL[mt][1], aL[mt][2], aL[mt][3], ad + 16384u);
                }
                const int rl = kb * 16 + rl16;   // l row in chunk
#pragma unroll
                for (int nt = 0; nt < 4; nt++) {
                    const int oc = warp_n * 4 + nt;
                    const uint32_t bd = bbase + (uint32_t)(rl * 256) + (uint32_t)((oc ^ (rl & 7)) << 4);
                    LDSM_X2_T(bH[nt][0], bH[nt][1], bd);
                    LDSM_X2_T(bL[nt][0], bL[nt][1], bd + 16384u);
                }
#pragma unroll
                for (int mt = 0; mt < 4; mt++)
#pragma unroll
                    for (int nt = 0; nt < 4; nt++) {
                        mma_bf16(acc[mt][nt], aH[mt], bH[nt]);
                        mma_bf16(acc[mt][nt], aH[mt], bL[nt]);
                        mma_bf16(acc[mt][nt], aL[mt], bH[nt]);
                    }
            }
        }
        __syncthreads();
        if (ck == 0) MIX_ISSUE(2);
    }
#undef MIX_ISSUE

    // epilogue: out = relu(acc + rowbias) + g_pe
    const int erow = (lane >> 2);
    const int ecol = 2 * (lane & 3);
#pragma unroll
    for (int mt = 0; mt < 4; mt++) {
        const int row = warp_m * 64 + mt * 16 + erow;
        const float rb0 = s_rb[row];
        const float rb1 = s_rb[row + 8];
#pragma unroll
        for (int nt = 0; nt < 4; nt++) {
            const int lc = warp_n * 32 + nt * 8 + ecol;
            const size_t base0 = ((size_t)b * 128 + row) * 512 + n0 + lc;
            const size_t base1 = base0 + (size_t)8 * 512;
            float2 p0 = *(const float2*)(g_pe + base0);
            float2 p1 = *(const float2*)(g_pe + base1);
            float2 v0, v1;
            v0.x = fmaxf(acc[mt][nt][0] + rb0, 0.0f) + p0.x;
            v0.y = fmaxf(acc[mt][nt][1] + rb0, 0.0f) + p0.y;
            v1.x = fmaxf(acc[mt][nt][2] + rb1, 0.0f) + p1.x;
            v1.y = fmaxf(acc[mt][nt][3] + rb1, 0.0f) + p1.y;
            *(float2*)(out + base0) = v0;
            *(float2*)(out + base1) = v1;
        }
    }
}

// ---------------- prep ----------------
__global__ void prep_kernel(const float* __restrict__ conv_w, const float* __restrict__ pe_w2,
                            const float* __restrict__ pe_w1, const float* __restrict__ pe_b1,
                            const float* __restrict__ pe_g1, const float* __restrict__ pe_bb1,
                            const float* __restrict__ pe_m1, const float* __restrict__ pe_v1,
                            const float* __restrict__ lin_w_img, const float* __restrict__ lin_b_img,
                            const float* __restrict__ lin_w_pc,  const float* __restrict__ lin_b_pc)
{
    int idx = blockIdx.x * 256 + threadIdx.x;
    if (idx < W_TOTAL) {
        float v = (idx < W_PE2_OFF) ? conv_w[idx] : pe_w2[idx - W_PE2_OFF];
        __nv_bfloat16 h = __float2bfloat16(v);
        g_wh[idx] = h;
        g_wl[idx] = __float2bfloat16(v - __bfloat162float(h));
    }
    if (idx < 128 * 192) {
        const int krow = idx / 192, lcat = idx % 192;
        const int mod = krow >> 5, k = krow & 31;
        float w = 0.0f;
        if (mod == 0)      { if (lcat < 49)                 w = lin_w_img[k * 49 + lcat]; }
        else if (mod == 1) { if (lcat >= 49 && lcat < 98)   w = lin_w_img[(32 + k) * 49 + lcat - 49]; }
        else if (mod == 2) { if (lcat >= 98 && lcat < 130)  w = lin_w_pc[k * 32 + lcat - 98]; }
        else               { if (lcat >= 130 && lcat < 162) w = lin_w_pc[(32 + k) * 32 + lcat - 130]; }
        __nv_bfloat16 h = __float2bfloat16(w);
        g_mwh[idx] = h;
        g_mwl[idx] = __float2bfloat16(w - __bfloat162float(h));
    }
    if (idx < 128) {
        const int mod = idx >> 5, k = idx & 31;
        g_mlb[idx] = (mod == 0) ? lin_b_img[k] : (mod == 1) ? lin_b_img[32 + k]
                   : (mod == 2) ? lin_b_pc[k] : lin_b_pc[32 + k];
        float s = pe_g1[idx] * rsqrtf(pe_v1[idx] + EPS_BN);
        g_peA[idx * 4 + 0] = pe_w1[idx * 3 + 0] * s;
        g_peA[idx * 4 + 1] = pe_w1[idx * 3 + 1] * s;
        g_peA[idx * 4 + 2] = pe_w1[idx * 3 + 2] * s;
        g_peA[idx * 4 + 3] = (pe_b1[idx] - pe_m1[idx]) * s + pe_bb1[idx];
    }
}

// ---------------- threefry / FPS ----------------
__device__ __forceinline__ unsigned rotl32(unsigned x, int d) {
    return (x << d) | (x >> (32 - d));
}
#define TF_ROUND(x0, x1, r) do { x0 += x1; x1 = rotl32(x1, r); x1 ^= x0; } while (0)
__device__ __forceinline__ void threefry2x32(unsigned k0, unsigned k1,
                                             unsigned& x0, unsigned& x1) {
    const unsigned kx = 0x1BD11BDAu ^ k0 ^ k1;
    x0 += k0; x1 += k1;
    TF_ROUND(x0, x1, 13); TF_ROUND(x0, x1, 15); TF_ROUND(x0, x1, 26); TF_ROUND(x0, x1, 6);
    x0 += k1; x1 += kx + 1u;
    TF_ROUND(x0, x1, 17); TF_ROUND(x0, x1, 29); TF_ROUND(x0, x1, 16); TF_ROUND(x0, x1, 24);
    x0 += kx; x1 += k0 + 2u;
    TF_ROUND(x0, x1, 13); TF_ROUND(x0, x1, 15); TF_ROUND(x0, x1, 26); TF_ROUND(x0, x1, 6);
    x0 += k0; x1 += k1 + 3u;
    TF_ROUND(x0, x1, 17); TF_ROUND(x0, x1, 29); TF_ROUND(x0, x1, 16); TF_ROUND(x0, x1, 24);
    x0 += k1; x1 += kx + 4u;
    TF_ROUND(x0, x1, 13); TF_ROUND(x0, x1, 15); TF_ROUND(x0, x1, 26); TF_ROUND(x0, x1, 6);
    x0 += kx; x1 += k0 + 5u;
}
__device__ __forceinline__ uint32_t redux_max_u32(uint32_t v) {
    uint32_t r;
    asm("redux.sync.max.u32 %0, %1, 0xffffffff;" : "=r"(r) : "r"(v));
    return r;
}
__device__ __forceinline__ uint32_t redux_min_u32(uint32_t v) {
    uint32_t r;
    asm("redux.sync.min.u32 %0, %1, 0xffffffff;" : "=r"(r) : "r"(v));
    return r;
}

__global__ __launch_bounds__(512)
void fps_kernel(const float* __restrict__ pts, float* __restrict__ nxyz) {
    extern __shared__ float sh[];
    float* xs = sh;
    float* ys = sh + 4096;
    float* zs = sh + 8192;
    __shared__ uint32_t red_v[16];
    __shared__ uint32_t red_i[16];
    __shared__ int sm_far;

    const int b = blockIdx.x;
    const int tid = threadIdx.x;
    const int lane = tid & 31;
    const int warp = tid >> 5;
    const float* p = pts + (size_t)b * 4096 * 3;
    for (int i = tid; i < 4096; i += 512) {
        xs[i] = p[3 * i + 0];
        ys[i] = p[3 * i + 1];
        zs[i] = p[3 * i + 2];
    }
    if (tid == 0) {
        unsigned a0 = 0u, a1 = 1u;
        threefry2x32(0u, 42u, a0, a1);
        unsigned c0 = 0u, c1 = (unsigned)b;
        threefry2x32(a0, a1, c0, c1);
        sm_far = (int)((c0 ^ c1) & 4095u);
    }
    __syncthreads();

    float dist[8];
#pragma unroll
    for (int j = 0; j < 8; j++) dist[j] = 1e10f;

    float* outp = nxyz + (size_t)b * 128 * 3;
    for (int it = 0; it < 128; ++it) {
        const int far = sm_far;
        const float cx = xs[far], cy = ys[far], cz = zs[far];
        if (tid == 0) {
            outp[3 * it + 0] = cx;
            outp[3 * it + 1] = cy;
            outp[3 * it + 2] = cz;
        }
        float bv = -1.0f;
        int bi = 0;
#pragma unroll
        for (int j = 0; j < 8; j++) {
            const int pi = (j << 9) + tid;
            float dx = __fadd_rn(xs[pi], -cx);
            float dy = __fadd_rn(ys[pi], -cy);
            float dz = __fadd_rn(zs[pi], -cz);
            float s0 = __fmul_rn(dx, dx);
            float s1 = __fmul_rn(dy, dy);
            float s2 = __fmul_rn(dz, dz);
            float d  = __fadd_rn(__fadd_rn(s0, s1), s2);
            float nd = fminf(dist[j], d);
            dist[j] = nd;
            if (nd > bv) { bv = nd; bi = pi; }
        }
        uint32_t bvu = __float_as_uint(bv);
        uint32_t gv = redux_max_u32(bvu);
        uint32_t cand = (bvu == gv) ? (uint32_t)bi : 0xFFFFFFFFu;
        uint32_t gi = redux_min_u32(cand);
        if (lane == 0) { red_v[warp] = gv; red_i[warp] = gi; }
        __syncthreads();
        if (tid < 32) {
            uint32_t v = (lane < 16) ? red_v[lane] : 0u;
            uint32_t i = (lane < 16) ? red_i[lane] : 0xFFFFFFFFu;
            uint32_t gv2 = redux_max_u32(v);
            uint32_t cand2 = (v == gv2) ? i : 0xFFFFFFFFu;
            uint32_t gi2 = redux_min_u32(cand2);
            if (lane == 0) sm_far = (int)gi2;
        }
        __syncthreads();
    }
}

// ---------------- launch ----------------
extern "C" void kernel_launch(void* const* d_in, const int* in_sizes, int n_in,
                              void* d_out, int out_size) {
    (void)in_sizes; (void)n_in; (void)out_size;
    const float* rgb       = (const float*)d_in[0];
    const float* depth     = (const float*)d_in[1];
    const float* mmwave    = (const float*)d_in[2];
    const float* lidar     = (const float*)d_in[3];
    const float* pts       = (const float*)d_in[4];
    const float* conv_w    = (const float*)d_in[5];
    const float* conv_b    = (const float*)d_in[6];
    const float* bn_g      = (const float*)d_in[7];
    const float* bn_b      = (const float*)d_in[8];
    const float* bn_m      = (const float*)d_in[9];
    const float* bn_v      = (const float*)d_in[10];
    const float* lin_w_img = (const float*)d_in[11];
    const float* lin_b_img = (const float*)d_in[12];
    const float* lin_w_pc  = (const float*)d_in[13];
    const float* lin_b_pc  = (const float*)d_in[14];
    const float* pe_w1     = (const float*)d_in[15];
    const float* pe_b1     = (const float*)d_in[16];
    const float* pe_g1     = (const float*)d_in[17];
    const float* pe_bb1    = (const float*)d_in[18];
    const float* pe_m1     = (const float*)d_in[19];
    const float* pe_v1     = (const float*)d_in[20];
    const float* pe_w2     = (const float*)d_in[21];
    const float* pe_b2     = (const float*)d_in[22];
    const float* pe_g2     = (const float*)d_in[23];
    const float* pe_bb2    = (const float*)d_in[24];
    const float* pe_m2     = (const float*)d_in[25];
    const float* pe_v2     = (const float*)d_in[26];
    float* out = (float*)d_out;

    float* nx;
    cudaGetSymbolAddress((void**)&nx, g_newxyz);

    static cudaStream_t s2 = nullptr;
    static cudaEvent_t evA = nullptr, evP = nullptr, evB = nullptr;
    if (!s2) {
        cudaStreamCreateWithFlags(&s2, cudaStreamNonBlocking);
        cudaEventCreateWithFlags(&evA, cudaEventDisableTiming);
        cudaEventCreateWithFlags(&evP, cudaEventDisableTiming);
        cudaEventCreateWithFlags(&evB, cudaEventDisableTiming);
        cudaFuncSetAttribute(fps_kernel, cudaFuncAttributeMaxDynamicSharedMemorySize, 50176);
        cudaFuncSetAttribute(gemm4_async, cudaFuncAttributeMaxDynamicSharedMemorySize, G4_SMEM);
        cudaFuncSetAttribute(hmma_pe2, cudaFuncAttributeMaxDynamicSharedMemorySize, GEMM_SMEM);
        cudaFuncSetAttribute(mix_gemm, cudaFuncAttributeMaxDynamicSharedMemorySize, MIX_SMEM);
    }

    // fork: FPS on side stream
    cudaEventRecord(evA, 0);
    cudaStreamWaitEvent(s2, evA, 0);
    fps_kernel<<<256, 512, 49152, s2>>>(pts, nx);

    // main: prep then xsplit
    prep_kernel<<<(W_TOTAL + 255) / 256, 256>>>(conv_w, pe_w2, pe_w1, pe_b1,
                                                pe_g1, pe_bb1, pe_m1, pe_v1,
                                                lin_w_img, lin_b_img, lin_w_pc, lin_b_pc);
    cudaEventRecord(evP, 0);
    xsplit_kernel<<<10368, 512>>>(rgb, depth, mmwave, lidar);

    // side: pe2 (needs FPS + prep) -> g_pe
    cudaStreamWaitEvent(s2, evP, 0);
    hmma_pe2<<<dim3(4, 256), 256, GEMM_SMEM, s2>>>(pe_b2, pe_g2, pe_bb2, pe_m2, pe_v2);
    cudaEventRecord(evB, s2);

    // main: branch GEMMs (H presplit out) -> mix (ldmatrix.trans B, +pe add fused)
    gemm4_async<<<dim3(4, 162), 512, G4_SMEM>>>(conv_b, bn_g, bn_b, bn_m, bn_v);
    cudaStreamWaitEvent(0, evB, 0);
    mix_gemm<<<dim3(4, 256), 256, MIX_SMEM>>>(out);
}